// round 16
// baseline (speedup 1.0000x reference)
#include <cuda_runtime.h>

// ChamferLossSplit: B=256, N=M=256, D=4, PID_MAX=5.
// Inputs: target f32 [B,N,4], reco f32 [B,M,4], in_pid i32 [B,N], out_pid i32 [B,M]
// Output: f32[2] = (mean per_nonzero, mean per_zero)
//
// R13: broadcast-LDS + REDUX scheme. Each lane holds 8 target rows
// (rows lane+32k) so a warp holds all 256 rows. Warp w owns columns
// [32w,32w+32); step s broadcasts column 32w+s from smem (prefetched one step
// ahead). Because the warp holds all rows, one __reduce_min_sync per step
// yields the COMPLETE column min; lane s keeps it. No shuffle ring, no
// loop-carried serial chain. Row mins combine via 8 smem slabs as before.

#define NPTS 256
#define NWARP 8
#define RPL 8          // rows per lane
#define FULLMASK 0xffffffffu

__device__ float    g_scr0 = 0.0f, g_scr1 = 0.0f;
__device__ unsigned g_cnt = 0;

__device__ __forceinline__ float warp_sum(float v) {
    #pragma unroll
    for (int o = 16; o; o >>= 1) v += __shfl_xor_sync(FULLMASK, v, o);
    return v;
}

__global__ __launch_bounds__(NPTS) void chamfer_kernel(
    const float4* __restrict__ target,
    const float4* __restrict__ reco,
    const int* __restrict__ in_pid,
    const int* __restrict__ out_pid,
    float* __restrict__ out,
    float invB)
{
    __shared__ float4 s_s4[NPTS + 1];       // -2*reco, padded for prefetch
    __shared__ float  s_rn[NPTS + 1];       // |reco|^2 (INF if invalid), padded
    __shared__ float  s_row[NWARP * NPTS];  // per-warp partial row mins
    __shared__ float  s_red[6][NWARP];      // cross-warp sum buffer

    const int b = blockIdx.x;
    const int i = threadIdx.x;
    const int lane = i & 31;
    const int wid  = i >> 5;
    const float INF = __int_as_float(0x7f800000);
    const int base = b * NPTS;

    // ---- stage reco column i: s = -2*r, rn (INF-masked) ----
    const float4 r0 = reco[base + i];
    const int my = (out_pid[base + i] != 0);
    float rn_real = r0.x * r0.x;
    rn_real = fmaf(r0.y, r0.y, rn_real);
    rn_real = fmaf(r0.z, r0.z, rn_real);
    rn_real = fmaf(r0.w, r0.w, rn_real);
    const float rn0_raw = sqrtf(rn_real);          // ||r0|| for zero-pid sum
    s_s4[i] = make_float4(-2.0f * r0.x, -2.0f * r0.y, -2.0f * r0.z, -2.0f * r0.w);
    s_rn[i] = my ? rn_real : INF;
    if (i == 0) {
        s_s4[NPTS] = make_float4(0.0f, 0.0f, 0.0f, 0.0f);  // prefetch pad
        s_rn[NPTS] = 0.0f;
    }

    // ---- load 8 rows per lane (rows lane+32k); k==wid is this thread's own row i ----
    float4 tv[RPL];
    float tn[RPL], rm[RPL];
    int   mx_self = 0;
    float t0n_self = 0.0f;
    #pragma unroll
    for (int k = 0; k < RPL; k++) {
        const int row = lane + 32 * k;
        const float4 t0 = target[base + row];
        const int m = (in_pid[base + row] != 0);
        tv[k] = t0;
        float a = t0.x * t0.x;
        a = fmaf(t0.y, t0.y, a);
        a = fmaf(t0.z, t0.z, a);
        a = fmaf(t0.w, t0.w, a);
        if (k == wid) {  // row == i
            mx_self = m;
            t0n_self = sqrtf(a);
        }
        tn[k] = m ? a : INF;   // invalid row -> all its pair d2 = +INF
        rm[k] = INF;
    }
    __syncthreads();

    // ---- main loop: 32 broadcast columns per warp; REDUX gives full col min ----
    const int cb = 32 * wid;
    float4 sv = s_s4[cb];
    float  rn = s_rn[cb];
    unsigned cbits = 0x7f800000u;  // +inf bits; lane s keeps column cb+s
    #pragma unroll 4
    for (int s = 0; s < 32; s++) {
        // prefetch next column (broadcast LDS, latency hidden under the math)
        const float4 sv_n = s_s4[cb + s + 1];
        const float  rn_n = s_rn[cb + s + 1];

        float d2[RPL];
        #pragma unroll
        for (int k = 0; k < RPL; k++) {
            float acc = fmaf(tv[k].w, sv.w, tn[k]);
            acc = fmaf(tv[k].z, sv.z, acc);
            acc = fmaf(tv[k].y, sv.y, acc);
            acc = fmaf(tv[k].x, sv.x, acc);
            d2[k] = acc + rn;                 // tn + rn - 2*dot
            rm[k] = fminf(rm[k], d2[k]);
        }
        const float m0 = fminf(d2[0], d2[1]);
        const float m1 = fminf(d2[2], d2[3]);
        const float m2 = fminf(d2[4], d2[5]);
        const float m3 = fminf(d2[6], d2[7]);
        const float tr = fmaxf(fminf(fminf(m0, m1), fminf(m2, m3)), 0.0f);
        // warp holds ALL 256 rows -> this is the complete min of column cb+s
        const unsigned red = __reduce_min_sync(FULLMASK, __float_as_uint(tr));
        if (lane == s) cbits = red;

        sv = sv_n; rn = rn_n;
    }
    const float cmin = __uint_as_float(cbits);  // full column min for column i

    // ---- combine per-warp partial row mins via smem slabs ----
    #pragma unroll
    for (int k = 0; k < RPL; k++)
        s_row[wid * NPTS + lane + 32 * k] = rm[k];
    __syncthreads();

    float rowm = s_row[i];
    #pragma unroll
    for (int w = 1; w < NWARP; w++) rowm = fminf(rowm, s_row[w * NPTS + i]);

    // ---- per-thread contributions (sqrt clamped: dot-trick can round <0) ----
    float v[6];
    v[0] = mx_self ? 1.0f : 0.0f;                              // sum fx
    v[1] = my ? 1.0f : 0.0f;                                   // sum fy
    v[2] = mx_self ? sqrtf(fmaxf(rowm, 0.0f)) : 0.0f;          // sum_xy
    v[3] = my ? sqrtf(cmin) : 0.0f;                            // sum_yx (already clamped)
    v[4] = mx_self ? t0n_self : 0.0f;                          // fallback sum ||x||
    v[5] = my ? 0.0f : rn0_raw;                                // sum ||y|| zero-pid

    #pragma unroll
    for (int k = 0; k < 6; k++) {
        const float ws = warp_sum(v[k]);
        if (lane == 0) s_red[k][wid] = ws;
    }
    __syncthreads();

    if (i == 0) {
        float s[6];
        #pragma unroll
        for (int k = 0; k < 6; k++) {
            float acc = 0.0f;
            #pragma unroll
            for (int w = 0; w < NWARP; w++) acc += s_red[k][w];
            s[k] = acc;
        }
        const float sum_fx = s[0], sum_fy = s[1];
        const float sum_xy = s[2], sum_yx = s[3];
        const float sum_fb = s[4], sum_z  = s[5];

        const float n_in  = fmaxf(1.0f, sum_fx);
        const float n_out = fmaxf(1.0f, sum_fy);

        float per_nonzero;
        if (sum_fy == 0.0f) {
            per_nonzero = sum_fb / n_in;              // no valid reco
        } else if (sum_fx == 0.0f) {
            per_nonzero = 0.0f;                        // no valid target
        } else {
            per_nonzero = 0.5f * (sum_xy / n_out + sum_yx / n_in);
        }
        const float per_zero = sum_z / fmaxf(1.0f, (float)NPTS - sum_fy);

        // last-block reduction: accumulate in device scratch, winner writes
        // d_out and re-zeros scratch so the next graph replay starts clean.
        atomicAdd(&g_scr0, per_nonzero * invB);
        atomicAdd(&g_scr1, per_zero * invB);
        __threadfence();
        const unsigned old = atomicAdd(&g_cnt, 1u);
        if (old == gridDim.x - 1) {
            __threadfence();
            volatile float* vs0 = &g_scr0;
            volatile float* vs1 = &g_scr1;
            const float o0 = *vs0;
            const float o1 = *vs1;
            out[0] = o0;
            out[1] = o1;
            *vs0 = 0.0f;
            *vs1 = 0.0f;
            __threadfence();
            g_cnt = 0;
        }
    }
}

extern "C" void kernel_launch(void* const* d_in, const int* in_sizes, int n_in,
                              void* d_out, int out_size)
{
    const float4* target  = (const float4*)d_in[0];
    const float4* reco    = (const float4*)d_in[1];
    const int*    in_pid  = (const int*)d_in[2];
    const int*    out_pid = (const int*)d_in[3];
    float*        out     = (float*)d_out;

    const int B = in_sizes[2] / NPTS;

    chamfer_kernel<<<B, NPTS>>>(target, reco, in_pid, out_pid, out, 1.0f / (float)B);
}